// round 3
// baseline (speedup 1.0000x reference)
#include <cuda_runtime.h>
#include <cuda_bf16.h>
#include <cstdint>

#define BB 256
#define HH 1024
#define LL 4
#define DKV 512      // HKV*D
#define II 4096
#define VV 1027
#define CC 16
#define REPW 50
#define INF_F __int_as_float(0x7f800000)

// ---------------- scratch (device globals; no allocation) ----------------
__device__ float g_h[BB*HH];
__device__ float g_x[BB*HH];
__device__ float g_v[BB*DKV];
__device__ float g_g1[BB*II];
__device__ float g_g2[BB*II];
__device__ float g_m[BB*II];
__device__ float g_logits[BB*VV];
__device__ float g_woP[LL*DKV*HH];

// ---------------- threefry2x32 (JAX exact) ----------------
#define TF_ROUND(x0,x1,r) { x0 += x1; x1 = (x1<<(r))|(x1>>(32-(r))); x1 ^= x0; }
__host__ __device__ __forceinline__ void threefry2x32(unsigned k0, unsigned k1,
                                                      unsigned c0, unsigned c1,
                                                      unsigned* o0, unsigned* o1) {
  unsigned ks2 = k0 ^ k1 ^ 0x1BD11BDAu;
  unsigned x0 = c0 + k0, x1 = c1 + k1;
  TF_ROUND(x0,x1,13) TF_ROUND(x0,x1,15) TF_ROUND(x0,x1,26) TF_ROUND(x0,x1,6)
  x0 += k1;  x1 += ks2 + 1u;
  TF_ROUND(x0,x1,17) TF_ROUND(x0,x1,29) TF_ROUND(x0,x1,16) TF_ROUND(x0,x1,24)
  x0 += ks2; x1 += k0 + 2u;
  TF_ROUND(x0,x1,13) TF_ROUND(x0,x1,15) TF_ROUND(x0,x1,26) TF_ROUND(x0,x1,6)
  x0 += k0;  x1 += k1 + 3u;
  TF_ROUND(x0,x1,17) TF_ROUND(x0,x1,29) TF_ROUND(x0,x1,16) TF_ROUND(x0,x1,24)
  x0 += k1;  x1 += ks2 + 4u;
  TF_ROUND(x0,x1,13) TF_ROUND(x0,x1,15) TF_ROUND(x0,x1,26) TF_ROUND(x0,x1,6)
  x0 += ks2; x1 += k0 + 5u;
  *o0 = x0; *o1 = x1;
}

// ---------------- small kernels ----------------
__global__ void copy_kernel(const float* __restrict__ in, float* __restrict__ out, int n) {
  int i = blockIdx.x*blockDim.x + threadIdx.x;
  if (i < n) out[i] = in[i];
}

// fold repeat(v,2)@wo into woP[512,1024]
__global__ void wop_kernel(const float* __restrict__ wo, float* __restrict__ out) {
  int idx = blockIdx.x*blockDim.x + threadIdx.x;
  if (idx >= LL*DKV*HH) return;
  int l = idx >> 19;            // / (512*1024)
  int rem = idx & 524287;
  int s = rem >> 10, n = rem & 1023;
  int hv = s >> 6, d = s & 63;
  const float* w = wo + ((size_t)l << 20);   // l*1024*1024
  out[idx] = w[((hv*2)*64 + d)*1024 + n] + w[((hv*2+1)*64 + d)*1024 + n];
}

__global__ void rms_kernel(const float* __restrict__ in, const float* __restrict__ w,
                           float* __restrict__ out) {
  int b = blockIdx.x, t = threadIdx.x;
  const float* row = in + (size_t)b*HH;
  __shared__ float red[256];
  float s = 0.f;
  #pragma unroll
  for (int j = t; j < HH; j += 256) { float v = row[j]; s += v*v; }
  red[t] = s; __syncthreads();
  for (int st = 128; st > 0; st >>= 1) { if (t < st) red[t] += red[t+st]; __syncthreads(); }
  float r = 1.0f / sqrtf(red[0]*(1.0f/HH) + 1e-6f);
  for (int j = t; j < HH; j += 256) out[(size_t)b*HH + j] = row[j]*r*w[j];
}

__global__ void swiglu_kernel(const float* __restrict__ g1, const float* __restrict__ g2,
                              float* __restrict__ m, int n) {
  int i = blockIdx.x*blockDim.x + threadIdx.x;
  if (i < n) {
    float g = g1[i];
    float s = __fdiv_rn(1.f, __fadd_rn(1.f, expf(-g)));
    m[i] = g*s*g2[i];
  }
}

// ---------------- SGEMM: C[M,N] = A[M,K] @ B (+C if RES). BT=1 -> B stored [N,K]
template<int BT, int RES>
__global__ void sgemm(const float* __restrict__ A, const float* __restrict__ B,
                      float* __restrict__ C, int M, int N, int K) {
  __shared__ __align__(16) float As[16][64];
  __shared__ __align__(16) float Bs[16][64];
  int tid = threadIdx.x;
  int tx = tid & 15, ty = tid >> 4;
  int m0 = blockIdx.y*64, n0 = blockIdx.x*64;
  float acc[4][4];
  #pragma unroll
  for (int i = 0; i < 4; i++)
    #pragma unroll
    for (int j = 0; j < 4; j++) acc[i][j] = 0.f;
  int ar = tid >> 2, ac = (tid & 3) << 2;
  for (int k0 = 0; k0 < K; k0 += 16) {
    float4 av = *(const float4*)(A + (size_t)(m0+ar)*K + k0 + ac);
    As[ac+0][ar] = av.x; As[ac+1][ar] = av.y; As[ac+2][ar] = av.z; As[ac+3][ar] = av.w;
    if (BT == 0) {
      int br = tid >> 4, bc = (tid & 15) << 2;
      float4 bv = *(const float4*)(B + (size_t)(k0+br)*N + n0 + bc);
      *(float4*)&Bs[br][bc] = bv;
    } else {
      int nr = tid >> 2, kc = (tid & 3) << 2;
      int n = n0 + nr;
      float4 bv = make_float4(0.f,0.f,0.f,0.f);
      if (n < N) bv = *(const float4*)(B + (size_t)n*K + k0 + kc);
      Bs[kc+0][nr] = bv.x; Bs[kc+1][nr] = bv.y; Bs[kc+2][nr] = bv.z; Bs[kc+3][nr] = bv.w;
    }
    __syncthreads();
    #pragma unroll
    for (int k = 0; k < 16; k++) {
      float4 a = *(const float4*)&As[k][ty << 2];
      float4 b = *(const float4*)&Bs[k][tx << 2];
      float aa[4] = {a.x,a.y,a.z,a.w}, bb[4] = {b.x,b.y,b.z,b.w};
      #pragma unroll
      for (int i = 0; i < 4; i++)
        #pragma unroll
        for (int j = 0; j < 4; j++) acc[i][j] = fmaf(aa[i], bb[j], acc[i][j]);
    }
    __syncthreads();
  }
  #pragma unroll
  for (int i = 0; i < 4; i++) {
    int m = m0 + (ty << 2) + i;
    #pragma unroll
    for (int j = 0; j < 4; j++) {
      int n = n0 + (tx << 2) + j;
      if (BT == 0 || n < N) {
        float v = acc[i][j];
        if (RES) v += C[(size_t)m*N + n];
        C[(size_t)m*N + n] = v;
      }
    }
  }
}

// ---------------- rep penalty + top-k + top-p + gumbel sample + embed gather ----------
__global__ void sample_kernel(const float* __restrict__ logits, const int* __restrict__ hist,
                              const int* __restrict__ gsp, int step,
                              unsigned k0, unsigned k1,
                              float* __restrict__ out,
                              const float* __restrict__ embed, float* __restrict__ hnext,
                              int do_embed) {
  int b = blockIdx.x, t = threadIdx.x;
  __shared__ float sl[VV];
  __shared__ float wk[VV];
  __shared__ float cv[VV];
  __shared__ int   ci[VV];
  __shared__ float rv[256];
  __shared__ int   ri[256];
  __shared__ int   cnt;
  __shared__ float thrS;

  for (int v = t; v < VV; v += 256) sl[v] = logits[(size_t)b*VV + v];
  if (t == 0) cnt = 0;
  __syncthreads();

  // repetition penalty on raw logits (reads of originals happen before writes)
  int gs = *gsp;
  int w0 = gs - REPW; if (w0 < 0) w0 = 0;
  int wn = gs - w0;
  float cur = 0.f; int tk = -1;
  if (t < wn) { tk = hist[((size_t)b*200 + w0 + t)*CC + step]; cur = sl[tk]; }
  __syncthreads();
  if (t < wn) {
    float nw = (cur < 0.f) ? __fmul_rn(cur, 1.1f) : __fdiv_rn(cur, 1.1f);
    sl[tk] = nw;  // duplicates write identical value
  }
  __syncthreads();

  // temperature
  for (int v = t; v < VV; v += 256) { float x = __fdiv_rn(sl[v], 0.8f); sl[v] = x; wk[v] = x; }
  __syncthreads();

  // top-k: 30 iterations of remove-max -> 30th largest value
  for (int it = 0; it < 30; it++) {
    float bv = -INF_F; int bi = 0;
    for (int v = t; v < VV; v += 256) { float x = wk[v]; if (x > bv) { bv = x; bi = v; } }
    rv[t] = bv; ri[t] = bi; __syncthreads();
    for (int st = 128; st > 0; st >>= 1) {
      if (t < st) { if (rv[t+st] > rv[t]) { rv[t] = rv[t+st]; ri[t] = ri[t+st]; } }
      __syncthreads();
    }
    if (t == 0) { wk[ri[0]] = -INF_F; if (it == 29) thrS = rv[0]; }
    __syncthreads();
  }
  float thr = thrS;

  // candidates: l >= thr kept (ties kept, like where(l < thr, -inf))
  for (int v = t; v < VV; v += 256) {
    float x = sl[v];
    if (x >= thr) { int p = atomicAdd(&cnt, 1); cv[p] = x; ci[p] = v; }
  }
  __syncthreads();
  int n = cnt;

  if (t == 0) {
    // stable ascending sort (value, then original index) — matches jnp.argsort
    for (int i = 1; i < n; i++) {
      float kv = cv[i]; int ki = ci[i]; int j = i - 1;
      while (j >= 0 && (cv[j] > kv || (cv[j] == kv && ci[j] > ki))) {
        cv[j+1] = cv[j]; ci[j+1] = ci[j]; j--;
      }
      cv[j+1] = kv; ci[j+1] = ki;
    }
    // softmax (max-subtracted) then sequential cumsum; mask cp <= 1-top_p = 0.4
    float mx = cv[n-1];
    float total = 0.f;
    for (int j = 0; j < n; j++) { wk[j] = expf(cv[j] - mx); total += wk[j]; }
    float run = 0.f;
    for (int j = 0; j < n; j++) {
      run = __fadd_rn(run, __fdiv_rn(wk[j], total));
      if (run <= 0.4f) cv[j] = -INF_F;
    }
  }
  __syncthreads();

  // gumbel (JAX partitionable threefry: bits = o0^o1 of threefry(key,(0,m))) + argmax
  float bs = -INF_F; int bidx = 0x7fffffff;
  for (int j = t; j < n; j += 256) {
    float x = cv[j];
    if (x > -INF_F) {
      unsigned m = (unsigned)(b*VV + ci[j]);
      unsigned o0, o1;
      threefry2x32(k0, k1, 0u, m, &o0, &o1);
      unsigned bits = o0 ^ o1;
      float u = __uint_as_float((bits >> 9) | 0x3f800000u) - 1.0f;
      u = __fadd_rn(__fmul_rn(u, 1.0f), 1.17549435e-38f);
      u = fmaxf(1.17549435e-38f, u);
      float g = -logf(-logf(u));
      float sc = __fadd_rn(x, g);
      if (sc > bs || (sc == bs && ci[j] < bidx)) { bs = sc; bidx = ci[j]; }
    }
  }
  rv[t] = bs; ri[t] = bidx; __syncthreads();
  for (int st = 128; st > 0; st >>= 1) {
    if (t < st) {
      if (rv[t+st] > rv[t] || (rv[t+st] == rv[t] && ri[t+st] < ri[t])) {
        rv[t] = rv[t+st]; ri[t] = ri[t+st];
      }
    }
    __syncthreads();
  }
  int best = ri[0];
  // __output__ is float32: write the token VALUE as a float, not raw int bits.
  if (t == 0) out[b*CC + step] = (float)best;
  if (do_embed) {
    const float* e = embed + (size_t)best*HH;
    for (int j = t; j < HH; j += 256) hnext[(size_t)b*HH + j] = e[j];
  }
}

// ---------------- driver ----------------
extern "C" void kernel_launch(void* const* d_in, const int* in_sizes, int n_in,
                              void* d_out, int out_size) {
  const float* backbone = (const float*)d_in[0];
  const int*   hist     = (const int*)d_in[1];
  const int*   gsp      = (const int*)d_in[2];
  const float* embed    = (const float*)d_in[3];
  const float* lmh      = (const float*)d_in[4];
  const float* w_in     = (const float*)d_in[5];
  const float* w_v      = (const float*)d_in[8];
  const float* w_o      = (const float*)d_in[11];
  const float* w_post   = (const float*)d_in[12];
  const float* w_g      = (const float*)d_in[13];
  const float* w_u      = (const float*)d_in[14];
  const float* w_d      = (const float*)d_in[15];
  const float* fnorm    = (const float*)d_in[16];
  float* out = (float*)d_out;
  (void)in_sizes; (void)n_in; (void)out_size;

  float *ph, *px, *pv, *pg1, *pg2, *pm, *plog, *pwoP;
  cudaGetSymbolAddress((void**)&ph,   g_h);
  cudaGetSymbolAddress((void**)&px,   g_x);
  cudaGetSymbolAddress((void**)&pv,   g_v);
  cudaGetSymbolAddress((void**)&pg1,  g_g1);
  cudaGetSymbolAddress((void**)&pg2,  g_g2);
  cudaGetSymbolAddress((void**)&pm,   g_m);
  cudaGetSymbolAddress((void**)&plog, g_logits);
  cudaGetSymbolAddress((void**)&pwoP, g_woP);

  // per-step keys: split(key(1234), 16) under partitionable threefry:
  // key_i = threefry2x32((0,1234), (0, i))
  unsigned key0[CC], key1[CC];
  for (int i = 0; i < CC; i++) threefry2x32(0u, 1234u, 0u, (unsigned)i, &key0[i], &key1[i]);

  copy_kernel<<<(BB*HH + 255)/256, 256>>>(backbone, ph, BB*HH);
  wop_kernel<<<(LL*DKV*HH + 255)/256, 256>>>(w_o, pwoP);

  for (int i = 0; i < CC; i++) {
    for (int l = 0; l < LL; l++) {
      rms_kernel<<<BB, 256>>>(ph, w_in + (size_t)l*HH, px);
      sgemm<0,0><<<dim3(DKV/64, BB/64), 256>>>(px, w_v + (size_t)l*HH*DKV, pv, BB, DKV, HH);
      sgemm<0,1><<<dim3(HH/64, BB/64), 256>>>(pv, pwoP + (size_t)l*DKV*HH, ph, BB, HH, DKV);
      rms_kernel<<<BB, 256>>>(ph, w_post + (size_t)l*HH, px);
      sgemm<0,0><<<dim3(II/64, BB/64), 256>>>(px, w_g + (size_t)l*HH*II, pg1, BB, II, HH);
      sgemm<0,0><<<dim3(II/64, BB/64), 256>>>(px, w_u + (size_t)l*HH*II, pg2, BB, II, HH);
      swiglu_kernel<<<(BB*II + 255)/256, 256>>>(pg1, pg2, pm, BB*II);
      sgemm<0,1><<<dim3(HH/64, BB/64), 256>>>(pm, w_d + (size_t)l*II*HH, ph, BB, HH, II);
    }
    rms_kernel<<<BB, 256>>>(ph, fnorm, px);
    sgemm<1,0><<<dim3((VV + 63)/64, BB/64), 256>>>(px, lmh + (size_t)i*VV*HH, plog, BB, VV, HH);
    int do_embed = (i < CC - 1) ? 1 : 0;
    const float* etab = embed + (size_t)(do_embed ? (i + 1) : 0)*VV*HH;
    sample_kernel<<<BB, 256>>>(plog, hist, gsp, i, key0[i], key1[i], out, etab, ph, do_embed);
  }
}

// round 4
// speedup vs baseline: 1.6841x; 1.6841x over previous
#include <cuda_runtime.h>
#include <cuda_bf16.h>
#include <cstdint>

#define BB 256
#define HH 1024
#define LL 4
#define DKV 512      // HKV*D
#define II 4096
#define VV 1027
#define CC 16
#define REPW 50
#define INF_F __int_as_float(0x7f800000)

// ---------------- scratch (device globals; no allocation) ----------------
__device__ float g_h[BB*HH];
__device__ float g_x[BB*HH];
__device__ float g_g1[BB*II];
__device__ float g_m[BB*II];
__device__ float g_logits[BB*VV];
__device__ float g_woP[LL*DKV*HH];
__device__ float g_Wc[LL*HH*HH];        // folded wv@woP per layer
__device__ float g_part[2103296];       // split-K partials (max: lm 8*256*1027)

// ---------------- threefry2x32 (JAX exact) ----------------
#define TF_ROUND(x0,x1,r) { x0 += x1; x1 = (x1<<(r))|(x1>>(32-(r))); x1 ^= x0; }
__host__ __device__ __forceinline__ void threefry2x32(unsigned k0, unsigned k1,
                                                      unsigned c0, unsigned c1,
                                                      unsigned* o0, unsigned* o1) {
  unsigned ks2 = k0 ^ k1 ^ 0x1BD11BDAu;
  unsigned x0 = c0 + k0, x1 = c1 + k1;
  TF_ROUND(x0,x1,13) TF_ROUND(x0,x1,15) TF_ROUND(x0,x1,26) TF_ROUND(x0,x1,6)
  x0 += k1;  x1 += ks2 + 1u;
  TF_ROUND(x0,x1,17) TF_ROUND(x0,x1,29) TF_ROUND(x0,x1,16) TF_ROUND(x0,x1,24)
  x0 += ks2; x1 += k0 + 2u;
  TF_ROUND(x0,x1,13) TF_ROUND(x0,x1,15) TF_ROUND(x0,x1,26) TF_ROUND(x0,x1,6)
  x0 += k0;  x1 += k1 + 3u;
  TF_ROUND(x0,x1,17) TF_ROUND(x0,x1,29) TF_ROUND(x0,x1,16) TF_ROUND(x0,x1,24)
  x0 += k1;  x1 += ks2 + 4u;
  TF_ROUND(x0,x1,13) TF_ROUND(x0,x1,15) TF_ROUND(x0,x1,26) TF_ROUND(x0,x1,6)
  x0 += ks2; x1 += k0 + 5u;
  *o0 = x0; *o1 = x1;
}

// ---------------- small kernels ----------------
__global__ void copy_kernel(const float* __restrict__ in, float* __restrict__ out, int n) {
  int i = blockIdx.x*blockDim.x + threadIdx.x;
  if (i < n) out[i] = in[i];
}

// fold repeat(v,2)@wo into woP[512,1024]
__global__ void wop_kernel(const float* __restrict__ wo, float* __restrict__ out) {
  int idx = blockIdx.x*blockDim.x + threadIdx.x;
  if (idx >= LL*DKV*HH) return;
  int l = idx >> 19;
  int rem = idx & 524287;
  int s = rem >> 10, n = rem & 1023;
  int hv = s >> 6, d = s & 63;
  const float* w = wo + ((size_t)l << 20);
  out[idx] = w[((hv*2)*64 + d)*1024 + n] + w[((hv*2+1)*64 + d)*1024 + n];
}

__global__ void rms_kernel(const float* __restrict__ in, const float* __restrict__ w,
                           float* __restrict__ out) {
  int b = blockIdx.x, t = threadIdx.x;
  const float* row = in + (size_t)b*HH;
  __shared__ float red[256];
  float s = 0.f;
  #pragma unroll
  for (int j = t; j < HH; j += 256) { float v = row[j]; s += v*v; }
  red[t] = s; __syncthreads();
  for (int st = 128; st > 0; st >>= 1) { if (t < st) red[t] += red[t+st]; __syncthreads(); }
  float r = 1.0f / sqrtf(red[0]*(1.0f/HH) + 1e-6f);
  for (int j = t; j < HH; j += 256) out[(size_t)b*HH + j] = row[j]*r*w[j];
}

// ---------------- split-K reduce (+ optional residual, optional swiglu) -------------
__global__ void reduce_kernel(const float* __restrict__ P, float* __restrict__ out,
                              const float* __restrict__ resid, const float* __restrict__ aux,
                              int S, int MN4) {
  int i = blockIdx.x*blockDim.x + threadIdx.x;
  if (i >= MN4) return;
  const float4* P4 = (const float4*)P;
  float4 s = P4[i];
  for (int t = 1; t < S; t++) {
    float4 p = P4[(size_t)t*MN4 + i];
    s.x += p.x; s.y += p.y; s.z += p.z; s.w += p.w;
  }
  if (resid) {
    float4 r = ((const float4*)resid)[i];
    s.x += r.x; s.y += r.y; s.z += r.z; s.w += r.w;
  }
  if (aux) {
    float4 g = ((const float4*)aux)[i];
    float sx = __fdiv_rn(1.f, __fadd_rn(1.f, expf(-g.x)));
    float sy = __fdiv_rn(1.f, __fadd_rn(1.f, expf(-g.y)));
    float sz = __fdiv_rn(1.f, __fadd_rn(1.f, expf(-g.z)));
    float sw = __fdiv_rn(1.f, __fadd_rn(1.f, expf(-g.w)));
    s.x = g.x*sx*s.x; s.y = g.y*sy*s.y; s.z = g.z*sz*s.z; s.w = g.w*sw*s.w;
  }
  ((float4*)out)[i] = s;
}

// ---------------- SGEMM (f32x2): P[z][M,N] = A[M, Kc@z] @ B. BT=1 -> B stored [N,K]
template<int BT>
__global__ __launch_bounds__(256, 2)
void sgemm3(const float* __restrict__ A, const float* __restrict__ B,
            float* __restrict__ P, const int M, const int N, const int K) {
  __shared__ __align__(16) float As[16][256];   // m duplicated: As[k][2m],[2m+1]
  __shared__ __align__(16) float Bs[16][128];
  const int tid = threadIdx.x;
  const int tx = tid & 15, ty = tid >> 4;
  const int m0 = blockIdx.y * 128, n0 = blockIdx.x * 128;
  const int Kc = K / gridDim.z;
  const int ks = blockIdx.z * Kc;
  P += (size_t)blockIdx.z * M * N;

  unsigned long long acc[8][4];
  #pragma unroll
  for (int i = 0; i < 8; i++)
    #pragma unroll
    for (int j = 0; j < 4; j++) acc[i][j] = 0ull;

  const int ar = tid >> 1, ac = (tid & 1) * 8;

  for (int k0 = 0; k0 < Kc; k0 += 16) {
    // A tile 128x16 -> duplicated smem
    {
      const float* ap = A + (size_t)(m0 + ar) * K + ks + k0 + ac;
      float4 a0 = *(const float4*)ap;
      float4 a1 = *(const float4*)(ap + 4);
      float t8[8] = {a0.x,a0.y,a0.z,a0.w,a1.x,a1.y,a1.z,a1.w};
      #pragma unroll
      for (int i = 0; i < 8; i++)
        *(float2*)&As[ac + i][2*ar] = make_float2(t8[i], t8[i]);
    }
    // B tile 16x128
    if (BT == 0) {
      int kr = tid >> 4, nc = (tid & 15) * 8;
      const float* bp = B + (size_t)(ks + k0 + kr) * N + n0 + nc;
      *(float4*)&Bs[kr][nc]     = *(const float4*)bp;
      *(float4*)&Bs[kr][nc + 4] = *(const float4*)(bp + 4);
    } else {
      int nr = tid >> 1, kc = (tid & 1) * 8;
      int n = n0 + nr;
      float4 b0 = make_float4(0.f,0.f,0.f,0.f), b1 = b0;
      if (n < N) {
        const float* bp = B + (size_t)n * K + ks + k0 + kc;
        b0 = *(const float4*)bp; b1 = *(const float4*)(bp + 4);
      }
      float t8[8] = {b0.x,b0.y,b0.z,b0.w,b1.x,b1.y,b1.z,b1.w};
      #pragma unroll
      for (int i = 0; i < 8; i++) Bs[kc + i][nr] = t8[i];
    }
    __syncthreads();
    #pragma unroll
    for (int k = 0; k < 16; k++) {
      ulonglong2 a0 = *(const ulonglong2*)&As[k][ty*16];
      ulonglong2 a1 = *(const ulonglong2*)&As[k][ty*16 + 4];
      ulonglong2 a2 = *(const ulonglong2*)&As[k][ty*16 + 8];
      ulonglong2 a3 = *(const ulonglong2*)&As[k][ty*16 + 12];
      ulonglong2 b0 = *(const ulonglong2*)&Bs[k][tx*8];
      ulonglong2 b1 = *(const ulonglong2*)&Bs[k][tx*8 + 4];
      unsigned long long ap8[8] = {a0.x,a0.y,a1.x,a1.y,a2.x,a2.y,a3.x,a3.y};
      unsigned long long bp4[4] = {b0.x,b0.y,b1.x,b1.y};
      #pragma unroll
      for (int m = 0; m < 8; m++)
        #pragma unroll
        for (int q = 0; q < 4; q++)
          asm("fma.rn.f32x2 %0, %1, %2, %0;" : "+l"(acc[m][q]) : "l"(ap8[m]), "l"(bp4[q]));
    }
    __syncthreads();
  }

  #pragma unroll
  for (int m = 0; m < 8; m++) {
    int gm = m0 + ty*8 + m;
    float* row = P + (size_t)gm * N;
    #pragma unroll
    for (int q = 0; q < 4; q++) {
      float lo, hi;
      asm("mov.b64 {%0,%1}, %2;" : "=f"(lo), "=f"(hi) : "l"(acc[m][q]));
      int n = n0 + tx*8 + 2*q;
      if (BT == 0) {
        row[n] = lo; row[n+1] = hi;
      } else {
        if (n < N)     row[n] = lo;
        if (n + 1 < N) row[n+1] = hi;
      }
    }
  }
}

// ---------------- rep penalty + top-k + top-p + gumbel sample + embed gather ----------
__global__ void sample_kernel(const float* __restrict__ logits, const int* __restrict__ hist,
                              const int* __restrict__ gsp, int step,
                              unsigned k0, unsigned k1,
                              float* __restrict__ out,
                              const float* __restrict__ embed, float* __restrict__ hnext,
                              int do_embed) {
  int b = blockIdx.x, t = threadIdx.x;
  __shared__ float sl[VV];
  __shared__ float wk[VV];
  __shared__ float cv[VV];
  __shared__ int   ci[VV];
  __shared__ float rv[256];
  __shared__ int   ri[256];
  __shared__ int   cnt;
  __shared__ float thrS;

  for (int v = t; v < VV; v += 256) sl[v] = logits[(size_t)b*VV + v];
  if (t == 0) cnt = 0;
  __syncthreads();

  int gs = *gsp;
  int w0 = gs - REPW; if (w0 < 0) w0 = 0;
  int wn = gs - w0;
  float cur = 0.f; int tk = -1;
  if (t < wn) { tk = hist[((size_t)b*200 + w0 + t)*CC + step]; cur = sl[tk]; }
  __syncthreads();
  if (t < wn) {
    float nw = (cur < 0.f) ? __fmul_rn(cur, 1.1f) : __fdiv_rn(cur, 1.1f);
    sl[tk] = nw;
  }
  __syncthreads();

  for (int v = t; v < VV; v += 256) { float x = __fdiv_rn(sl[v], 0.8f); sl[v] = x; wk[v] = x; }
  __syncthreads();

  for (int it = 0; it < 30; it++) {
    float bv = -INF_F; int bi = 0;
    for (int v = t; v < VV; v += 256) { float x = wk[v]; if (x > bv) { bv = x; bi = v; } }
    rv[t] = bv; ri[t] = bi; __syncthreads();
    for (int st = 128; st > 0; st >>= 1) {
      if (t < st) { if (rv[t+st] > rv[t]) { rv[t] = rv[t+st]; ri[t] = ri[t+st]; } }
      __syncthreads();
    }
    if (t == 0) { wk[ri[0]] = -INF_F; if (it == 29) thrS = rv[0]; }
    __syncthreads();
  }
  float thr = thrS;

  for (int v = t; v < VV; v += 256) {
    float x = sl[v];
    if (x >= thr) { int p = atomicAdd(&cnt, 1); cv[p] = x; ci[p] = v; }
  }
  __syncthreads();
  int n = cnt;

  if (t == 0) {
    for (int i = 1; i < n; i++) {
      float kv = cv[i]; int ki = ci[i]; int j = i - 1;
      while (j >= 0 && (cv[j] > kv || (cv[j] == kv && ci[j] > ki))) {
        cv[j+1] = cv[j]; ci[j+1] = ci[j]; j--;
      }
      cv[j+1] = kv; ci[j+1] = ki;
    }
    float mx = cv[n-1];
    float total = 0.f;
    for (int j = 0; j < n; j++) { wk[j] = expf(cv[j] - mx); total += wk[j]; }
    float run = 0.f;
    for (int j = 0; j < n; j++) {
      run = __fadd_rn(run, __fdiv_rn(wk[j], total));
      if (run <= 0.4f) cv[j] = -INF_F;
    }
  }
  __syncthreads();

  float bs = -INF_F; int bidx = 0x7fffffff;
  for (int j = t; j < n; j += 256) {
    float x = cv[j];
    if (x > -INF_F) {
      unsigned m = (unsigned)(b*VV + ci[j]);
      unsigned o0, o1;
      threefry2x32(k0, k1, 0u, m, &o0, &o1);
      unsigned bits = o0 ^ o1;
      float u = __uint_as_float((bits >> 9) | 0x3f800000u) - 1.0f;
      u = __fadd_rn(__fmul_rn(u, 1.0f), 1.17549435e-38f);
      u = fmaxf(1.17549435e-38f, u);
      float g = -logf(-logf(u));
      float sc = __fadd_rn(x, g);
      if (sc > bs || (sc == bs && ci[j] < bidx)) { bs = sc; bidx = ci[j]; }
    }
  }
  rv[t] = bs; ri[t] = bidx; __syncthreads();
  for (int st = 128; st > 0; st >>= 1) {
    if (t < st) {
      if (rv[t+st] > rv[t] || (rv[t+st] == rv[t] && ri[t+st] < ri[t])) {
        rv[t] = rv[t+st]; ri[t] = ri[t+st];
      }
    }
    __syncthreads();
  }
  int best = ri[0];
  if (t == 0) out[b*CC + step] = (float)best;
  if (do_embed) {
    const float* e = embed + (size_t)best*HH;
    for (int j = t; j < HH; j += 256) hnext[(size_t)b*HH + j] = e[j];
  }
}

// ---------------- driver ----------------
extern "C" void kernel_launch(void* const* d_in, const int* in_sizes, int n_in,
                              void* d_out, int out_size) {
  const float* backbone = (const float*)d_in[0];
  const int*   hist     = (const int*)d_in[1];
  const int*   gsp      = (const int*)d_in[2];
  const float* embed    = (const float*)d_in[3];
  const float* lmh      = (const float*)d_in[4];
  const float* w_in     = (const float*)d_in[5];
  const float* w_v      = (const float*)d_in[8];
  const float* w_o      = (const float*)d_in[11];
  const float* w_post   = (const float*)d_in[12];
  const float* w_g      = (const float*)d_in[13];
  const float* w_u      = (const float*)d_in[14];
  const float* w_d      = (const float*)d_in[15];
  const float* fnorm    = (const float*)d_in[16];
  float* out = (float*)d_out;
  (void)in_sizes; (void)n_in; (void)out_size;

  float *ph, *px, *pg1, *pm, *plog, *pwoP, *pWc, *ppart;
  cudaGetSymbolAddress((void**)&ph,    g_h);
  cudaGetSymbolAddress((void**)&px,    g_x);
  cudaGetSymbolAddress((void**)&pg1,   g_g1);
  cudaGetSymbolAddress((void**)&pm,    g_m);
  cudaGetSymbolAddress((void**)&plog,  g_logits);
  cudaGetSymbolAddress((void**)&pwoP,  g_woP);
  cudaGetSymbolAddress((void**)&pWc,   g_Wc);
  cudaGetSymbolAddress((void**)&ppart, g_part);

  unsigned key0[CC], key1[CC];
  for (int i = 0; i < CC; i++) threefry2x32(0u, 1234u, 0u, (unsigned)i, &key0[i], &key1[i]);

  copy_kernel<<<(BB*HH + 255)/256, 256>>>(backbone, ph, BB*HH);
  wop_kernel<<<(LL*DKV*HH + 255)/256, 256>>>(w_o, pwoP);
  // precompute Wc[l] = wv[l] @ woP[l]  ([1024,512]@[512,1024] -> [1024,1024])
  for (int l = 0; l < LL; l++) {
    sgemm3<0><<<dim3(HH/128, HH/128, 1), 256>>>(
        w_v + (size_t)l*HH*DKV, pwoP + (size_t)l*DKV*HH, pWc + (size_t)l*HH*HH,
        HH, HH, DKV);
  }

  const int MN_H  = BB*HH;   // 262144
  const int MN_I  = BB*II;   // 1048576
  const int MN_V  = BB*VV;   // 262912

  for (int i = 0; i < CC; i++) {
    for (int l = 0; l < LL; l++) {
      rms_kernel<<<BB, 256>>>(ph, w_in + (size_t)l*HH, px);
      // attention collapsed: h += x @ Wc[l]   (split-K 8)
      sgemm3<0><<<dim3(HH/128, BB/128, 8), 256>>>(px, pWc + (size_t)l*HH*HH, ppart, BB, HH, HH);
      reduce_kernel<<<(MN_H/4 + 255)/256, 256>>>(ppart, ph, ph, nullptr, 8, MN_H/4);
      rms_kernel<<<BB, 256>>>(ph, w_post + (size_t)l*HH, px);
      // gate (split-K 2)
      sgemm3<0><<<dim3(II/128, BB/128, 2), 256>>>(px, w_g + (size_t)l*HH*II, ppart, BB, II, HH);
      reduce_kernel<<<(MN_I/4 + 255)/256, 256>>>(ppart, pg1, nullptr, nullptr, 2, MN_I/4);
      // up (split-K 2) then swiglu fused in reduce
      sgemm3<0><<<dim3(II/128, BB/128, 2), 256>>>(px, w_u + (size_t)l*HH*II, ppart, BB, II, HH);
      reduce_kernel<<<(MN_I/4 + 255)/256, 256>>>(ppart, pm, nullptr, pg1, 2, MN_I/4);
      // down (split-K 8) + residual
      sgemm3<0><<<dim3(HH/128, BB/128, 8), 256>>>(pm, w_d + (size_t)l*II*HH, ppart, BB, HH, II);
      reduce_kernel<<<(MN_H/4 + 255)/256, 256>>>(ppart, ph, ph, nullptr, 8, MN_H/4);
    }
    rms_kernel<<<BB, 256>>>(ph, fnorm, px);
    // lm head: B stored [V,H] (BT=1), split-K 8
    sgemm3<1><<<dim3((VV + 127)/128, BB/128, 8), 256>>>(px, lmh + (size_t)i*VV*HH, ppart, BB, VV, HH);
    reduce_kernel<<<(MN_V/4 + 255)/256, 256>>>(ppart, plog, nullptr, nullptr, 8, MN_V/4);
    int do_embed = (i < CC - 1) ? 1 : 0;
    const float* etab = embed + (size_t)(do_embed ? (i + 1) : 0)*VV*HH;
    sample_kernel<<<BB, 256>>>(plog, hist, gsp, i, key0[i], key1[i], out, etab, ph, do_embed);
  }
}

// round 5
// speedup vs baseline: 1.7733x; 1.0529x over previous
#include <cuda_runtime.h>
#include <cuda_bf16.h>
#include <cstdint>

#define BB 256
#define HH 1024
#define LL 4
#define DKV 512      // HKV*D
#define II 4096
#define VV 1027
#define CC 16
#define REPW 50
#define INF_F __int_as_float(0x7f800000)

// ---------------- scratch (device globals; no allocation) ----------------
__device__ float g_h[BB*HH];
__device__ float g_x[BB*HH];
__device__ float g_g1[BB*II];
__device__ float g_m[BB*II];
__device__ float g_logits[BB*VV];
__device__ float g_woP[LL*DKV*HH];
__device__ float g_Wc[LL*HH*HH];        // folded wv@woP per layer
__device__ float g_part[4206592];       // split-K partials (max: lm 16*256*1027)

// ---------------- threefry2x32 (JAX exact) ----------------
#define TF_ROUND(x0,x1,r) { x0 += x1; x1 = (x1<<(r))|(x1>>(32-(r))); x1 ^= x0; }
__host__ __device__ __forceinline__ void threefry2x32(unsigned k0, unsigned k1,
                                                      unsigned c0, unsigned c1,
                                                      unsigned* o0, unsigned* o1) {
  unsigned ks2 = k0 ^ k1 ^ 0x1BD11BDAu;
  unsigned x0 = c0 + k0, x1 = c1 + k1;
  TF_ROUND(x0,x1,13) TF_ROUND(x0,x1,15) TF_ROUND(x0,x1,26) TF_ROUND(x0,x1,6)
  x0 += k1;  x1 += ks2 + 1u;
  TF_ROUND(x0,x1,17) TF_ROUND(x0,x1,29) TF_ROUND(x0,x1,16) TF_ROUND(x0,x1,24)
  x0 += ks2; x1 += k0 + 2u;
  TF_ROUND(x0,x1,13) TF_ROUND(x0,x1,15) TF_ROUND(x0,x1,26) TF_ROUND(x0,x1,6)
  x0 += k0;  x1 += k1 + 3u;
  TF_ROUND(x0,x1,17) TF_ROUND(x0,x1,29) TF_ROUND(x0,x1,16) TF_ROUND(x0,x1,24)
  x0 += k1;  x1 += ks2 + 4u;
  TF_ROUND(x0,x1,13) TF_ROUND(x0,x1,15) TF_ROUND(x0,x1,26) TF_ROUND(x0,x1,6)
  x0 += ks2; x1 += k0 + 5u;
  *o0 = x0; *o1 = x1;
}

// ---------------- small kernels ----------------
__global__ void copy_kernel(const float* __restrict__ in, float* __restrict__ out, int n) {
  int i = blockIdx.x*blockDim.x + threadIdx.x;
  if (i < n) out[i] = in[i];
}

// fold repeat(v,2)@wo into woP[512,1024]
__global__ void wop_kernel(const float* __restrict__ wo, float* __restrict__ out) {
  int idx = blockIdx.x*blockDim.x + threadIdx.x;
  if (idx >= LL*DKV*HH) return;
  int l = idx >> 19;
  int rem = idx & 524287;
  int s = rem >> 10, n = rem & 1023;
  int hv = s >> 6, d = s & 63;
  const float* w = wo + ((size_t)l << 20);
  out[idx] = w[((hv*2)*64 + d)*1024 + n] + w[((hv*2+1)*64 + d)*1024 + n];
}

__global__ void rms_kernel(const float* __restrict__ in, const float* __restrict__ w,
                           float* __restrict__ out) {
  int b = blockIdx.x, t = threadIdx.x;
  const float* row = in + (size_t)b*HH;
  __shared__ float red[256];
  float s = 0.f;
  #pragma unroll
  for (int j = t; j < HH; j += 256) { float v = row[j]; s += v*v; }
  red[t] = s; __syncthreads();
  for (int st = 128; st > 0; st >>= 1) { if (t < st) red[t] += red[t+st]; __syncthreads(); }
  float r = 1.0f / sqrtf(red[0]*(1.0f/HH) + 1e-6f);
  for (int j = t; j < HH; j += 256) out[(size_t)b*HH + j] = row[j]*r*w[j];
}

// ---------------- split-K reduce (+ optional residual, optional swiglu) -------------
__global__ void reduce_kernel(const float* __restrict__ P, float* __restrict__ out,
                              const float* __restrict__ resid, const float* __restrict__ aux,
                              int S, int MN4) {
  int i = blockIdx.x*blockDim.x + threadIdx.x;
  if (i >= MN4) return;
  const float4* P4 = (const float4*)P;
  float4 s = P4[i];
  for (int t = 1; t < S; t++) {
    float4 p = P4[(size_t)t*MN4 + i];
    s.x += p.x; s.y += p.y; s.z += p.z; s.w += p.w;
  }
  if (resid) {
    float4 r = ((const float4*)resid)[i];
    s.x += r.x; s.y += r.y; s.z += r.z; s.w += r.w;
  }
  if (aux) {
    float4 g = ((const float4*)aux)[i];
    float sx = __fdiv_rn(1.f, __fadd_rn(1.f, expf(-g.x)));
    float sy = __fdiv_rn(1.f, __fadd_rn(1.f, expf(-g.y)));
    float sz = __fdiv_rn(1.f, __fadd_rn(1.f, expf(-g.z)));
    float sw = __fdiv_rn(1.f, __fadd_rn(1.f, expf(-g.w)));
    s.x = g.x*sx*s.x; s.y = g.y*sy*s.y; s.z = g.z*sz*s.z; s.w = g.w*sw*s.w;
  }
  ((float4*)out)[i] = s;
}

// ---------------- pipelined SGEMM (f32x2, 2-stage): P[z][M,N] = A[M,Kc@z] @ B
// BT=1 -> B stored [N,K]
template<int BT>
__global__ __launch_bounds__(256, 2)
void sgemm4(const float* __restrict__ A, const float* __restrict__ B,
            float* __restrict__ P, const int M, const int N, const int K) {
  __shared__ __align__(16) float As[2][16][256];   // m duplicated: [2m],[2m+1]
  __shared__ __align__(16) float Bs[2][16][128];
  const int tid = threadIdx.x;
  const int tx = tid & 15, ty = tid >> 4;
  const int m0 = blockIdx.y * 128, n0 = blockIdx.x * 128;
  const int Kc = K / gridDim.z;
  const int ks = blockIdx.z * Kc;
  P += (size_t)blockIdx.z * M * N;

  unsigned long long acc[8][4];
  #pragma unroll
  for (int i = 0; i < 8; i++)
    #pragma unroll
    for (int j = 0; j < 4; j++) acc[i][j] = 0ull;

  // A-load mapping: 128 rows x 16 k, 8 floats/thread
  const int ar = tid >> 1, ac = (tid & 1) * 8;
  const float* Abase = A + (size_t)(m0 + ar) * K + ks + ac;
  // B-load mapping
  const int b_kr = tid >> 4, b_nc = (tid & 15) * 8;          // BT==0
  const int b_nr = tid >> 1, b_kc = (tid & 1) * 8;           // BT==1
  const float* Bbase0 = B + (size_t)(ks + b_kr) * N + n0 + b_nc;
  const int bn1 = n0 + b_nr;
  const float* Bbase1 = B + (size_t)bn1 * K + ks + b_kc;

  float aR[8], bR[8];

  // prolog: load tile 0
  {
    float4 a0 = *(const float4*)Abase;
    float4 a1 = *(const float4*)(Abase + 4);
    aR[0]=a0.x; aR[1]=a0.y; aR[2]=a0.z; aR[3]=a0.w;
    aR[4]=a1.x; aR[5]=a1.y; aR[6]=a1.z; aR[7]=a1.w;
    if (BT == 0) {
      float4 b0 = *(const float4*)Bbase0;
      float4 b1 = *(const float4*)(Bbase0 + 4);
      bR[0]=b0.x; bR[1]=b0.y; bR[2]=b0.z; bR[3]=b0.w;
      bR[4]=b1.x; bR[5]=b1.y; bR[6]=b1.z; bR[7]=b1.w;
    } else {
      float4 b0 = make_float4(0.f,0.f,0.f,0.f), b1 = b0;
      if (bn1 < N) { b0 = *(const float4*)Bbase1; b1 = *(const float4*)(Bbase1 + 4); }
      bR[0]=b0.x; bR[1]=b0.y; bR[2]=b0.z; bR[3]=b0.w;
      bR[4]=b1.x; bR[5]=b1.y; bR[6]=b1.z; bR[7]=b1.w;
    }
    #pragma unroll
    for (int i = 0; i < 8; i++)
      *(float2*)&As[0][ac + i][2*ar] = make_float2(aR[i], aR[i]);
    if (BT == 0) {
      *(float4*)&Bs[0][b_kr][b_nc]     = make_float4(bR[0],bR[1],bR[2],bR[3]);
      *(float4*)&Bs[0][b_kr][b_nc + 4] = make_float4(bR[4],bR[5],bR[6],bR[7]);
    } else {
      #pragma unroll
      for (int i = 0; i < 8; i++) Bs[0][b_kc + i][b_nr] = bR[i];
    }
  }
  __syncthreads();

  const int nIter = Kc >> 4;
  for (int kt = 0; kt < nIter; kt++) {
    const int cur = kt & 1;
    const bool hasNext = (kt + 1 < nIter);
    // issue next tile's global loads early
    if (hasNext) {
      const float* ap = Abase + (kt + 1) * 16;
      float4 a0 = *(const float4*)ap;
      float4 a1 = *(const float4*)(ap + 4);
      aR[0]=a0.x; aR[1]=a0.y; aR[2]=a0.z; aR[3]=a0.w;
      aR[4]=a1.x; aR[5]=a1.y; aR[6]=a1.z; aR[7]=a1.w;
      if (BT == 0) {
        const float* bp = Bbase0 + (size_t)(kt + 1) * 16 * N;
        float4 b0 = *(const float4*)bp;
        float4 b1 = *(const float4*)(bp + 4);
        bR[0]=b0.x; bR[1]=b0.y; bR[2]=b0.z; bR[3]=b0.w;
        bR[4]=b1.x; bR[5]=b1.y; bR[6]=b1.z; bR[7]=b1.w;
      } else {
        float4 b0 = make_float4(0.f,0.f,0.f,0.f), b1 = b0;
        if (bn1 < N) {
          const float* bp = Bbase1 + (kt + 1) * 16;
          b0 = *(const float4*)bp; b1 = *(const float4*)(bp + 4);
        }
        bR[0]=b0.x; bR[1]=b0.y; bR[2]=b0.z; bR[3]=b0.w;
        bR[4]=b1.x; bR[5]=b1.y; bR[6]=b1.z; bR[7]=b1.w;
      }
    }
    // compute current stage
    #pragma unroll
    for (int k = 0; k < 16; k++) {
      ulonglong2 a0 = *(const ulonglong2*)&As[cur][k][ty*16];
      ulonglong2 a1 = *(const ulonglong2*)&As[cur][k][ty*16 + 4];
      ulonglong2 a2 = *(const ulonglong2*)&As[cur][k][ty*16 + 8];
      ulonglong2 a3 = *(const ulonglong2*)&As[cur][k][ty*16 + 12];
      ulonglong2 b0 = *(const ulonglong2*)&Bs[cur][k][tx*8];
      ulonglong2 b1 = *(const ulonglong2*)&Bs[cur][k][tx*8 + 4];
      unsigned long long ap8[8] = {a0.x,a0.y,a1.x,a1.y,a2.x,a2.y,a3.x,a3.y};
      unsigned long long bp4[4] = {b0.x,b0.y,b1.x,b1.y};
      #pragma unroll
      for (int m = 0; m < 8; m++)
        #pragma unroll
        for (int q = 0; q < 4; q++)
          asm("fma.rn.f32x2 %0, %1, %2, %0;" : "+l"(acc[m][q]) : "l"(ap8[m]), "l"(bp4[q]));
    }
    // stage next tile into the other buffer
    if (hasNext) {
      const int nxt = cur ^ 1;
      #pragma unroll
      for (int i = 0; i < 8; i++)
        *(float2*)&As[nxt][ac + i][2*ar] = make_float2(aR[i], aR[i]);
      if (BT == 0) {
        *(float4*)&Bs[nxt][b_kr][b_nc]     = make_float4(bR[0],bR[1],bR[2],bR[3]);
        *(float4*)&Bs[nxt][b_kr][b_nc + 4] = make_float4(bR[4],bR[5],bR[6],bR[7]);
      } else {
        #pragma unroll
        for (int i = 0; i < 8; i++) Bs[nxt][b_kc + i][b_nr] = bR[i];
      }
      __syncthreads();
    }
  }

  #pragma unroll
  for (int m = 0; m < 8; m++) {
    int gm = m0 + ty*8 + m;
    float* row = P + (size_t)gm * N;
    #pragma unroll
    for (int q = 0; q < 4; q++) {
      float lo, hi;
      asm("mov.b64 {%0,%1}, %2;" : "=f"(lo), "=f"(hi) : "l"(acc[m][q]));
      int n = n0 + tx*8 + 2*q;
      if (BT == 0) {
        row[n] = lo; row[n+1] = hi;
      } else {
        if (n < N)     row[n] = lo;
        if (n + 1 < N) row[n+1] = hi;
      }
    }
  }
}

// ---------------- rep penalty + top-k + top-p + gumbel sample + embed gather ----------
__global__ void sample_kernel(const float* __restrict__ logits, const int* __restrict__ hist,
                              const int* __restrict__ gsp, int step,
                              unsigned k0, unsigned k1,
                              float* __restrict__ out,
                              const float* __restrict__ embed, float* __restrict__ hnext,
                              int do_embed) {
  int b = blockIdx.x, t = threadIdx.x;
  __shared__ float sl[VV];
  __shared__ float wk[VV];
  __shared__ float cv[VV];
  __shared__ int   ci[VV];
  __shared__ float rv[256];
  __shared__ int   ri[256];
  __shared__ int   cnt;
  __shared__ float thrS;

  for (int v = t; v < VV; v += 256) sl[v] = logits[(size_t)b*VV + v];
  if (t == 0) cnt = 0;
  __syncthreads();

  int gs = *gsp;
  int w0 = gs - REPW; if (w0 < 0) w0 = 0;
  int wn = gs - w0;
  float cur = 0.f; int tk = -1;
  if (t < wn) { tk = hist[((size_t)b*200 + w0 + t)*CC + step]; cur = sl[tk]; }
  __syncthreads();
  if (t < wn) {
    float nw = (cur < 0.f) ? __fmul_rn(cur, 1.1f) : __fdiv_rn(cur, 1.1f);
    sl[tk] = nw;
  }
  __syncthreads();

  for (int v = t; v < VV; v += 256) { float x = __fdiv_rn(sl[v], 0.8f); sl[v] = x; wk[v] = x; }
  __syncthreads();

  for (int it = 0; it < 30; it++) {
    float bv = -INF_F; int bi = 0;
    for (int v = t; v < VV; v += 256) { float x = wk[v]; if (x > bv) { bv = x; bi = v; } }
    rv[t] = bv; ri[t] = bi; __syncthreads();
    for (int st = 128; st > 0; st >>= 1) {
      if (t < st) { if (rv[t+st] > rv[t]) { rv[t] = rv[t+st]; ri[t] = ri[t+st]; } }
      __syncthreads();
    }
    if (t == 0) { wk[ri[0]] = -INF_F; if (it == 29) thrS = rv[0]; }
    __syncthreads();
  }
  float thr = thrS;

  for (int v = t; v < VV; v += 256) {
    float x = sl[v];
    if (x >= thr) { int p = atomicAdd(&cnt, 1); cv[p] = x; ci[p] = v; }
  }
  __syncthreads();
  int n = cnt;

  if (t == 0) {
    for (int i = 1; i < n; i++) {
      float kv = cv[i]; int ki = ci[i]; int j = i - 1;
      while (j >= 0 && (cv[j] > kv || (cv[j] == kv && ci[j] > ki))) {
        cv[j+1] = cv[j]; ci[j+1] = ci[j]; j--;
      }
      cv[j+1] = kv; ci[j+1] = ki;
    }
    float mx = cv[n-1];
    float total = 0.f;
    for (int j = 0; j < n; j++) { wk[j] = expf(cv[j] - mx); total += wk[j]; }
    float run = 0.f;
    for (int j = 0; j < n; j++) {
      run = __fadd_rn(run, __fdiv_rn(wk[j], total));
      if (run <= 0.4f) cv[j] = -INF_F;
    }
  }
  __syncthreads();

  float bs = -INF_F; int bidx = 0x7fffffff;
  for (int j = t; j < n; j += 256) {
    float x = cv[j];
    if (x > -INF_F) {
      unsigned m = (unsigned)(b*VV + ci[j]);
      unsigned o0, o1;
      threefry2x32(k0, k1, 0u, m, &o0, &o1);
      unsigned bits = o0 ^ o1;
      float u = __uint_as_float((bits >> 9) | 0x3f800000u) - 1.0f;
      u = __fadd_rn(__fmul_rn(u, 1.0f), 1.17549435e-38f);
      u = fmaxf(1.17549435e-38f, u);
      float g = -logf(-logf(u));
      float sc = __fadd_rn(x, g);
      if (sc > bs || (sc == bs && ci[j] < bidx)) { bs = sc; bidx = ci[j]; }
    }
  }
  rv[t] = bs; ri[t] = bidx; __syncthreads();
  for (int st = 128; st > 0; st >>= 1) {
    if (t < st) {
      if (rv[t+st] > rv[t] || (rv[t+st] == rv[t] && ri[t+st] < ri[t])) {
        rv[t] = rv[t+st]; ri[t] = ri[t+st];
      }
    }
    __syncthreads();
  }
  int best = ri[0];
  if (t == 0) out[b*CC + step] = (float)best;
  if (do_embed) {
    const float* e = embed + (size_t)best*HH;
    for (int j = t; j < HH; j += 256) hnext[(size_t)b*HH + j] = e[j];
  }
}

// ---------------- driver ----------------
extern "C" void kernel_launch(void* const* d_in, const int* in_sizes, int n_in,
                              void* d_out, int out_size) {
  const float* backbone = (const float*)d_in[0];
  const int*   hist     = (const int*)d_in[1];
  const int*   gsp      = (const int*)d_in[2];
  const float* embed    = (const float*)d_in[3];
  const float* lmh      = (const float*)d_in[4];
  const float* w_in     = (const float*)d_in[5];
  const float* w_v      = (const float*)d_in[8];
  const float* w_o      = (const float*)d_in[11];
  const float* w_post   = (const float*)d_in[12];
  const float* w_g      = (const float*)d_in[13];
  const float* w_u      = (const float*)d_in[14];
  const float* w_d      = (const float*)d_in[15];
  const float* fnorm    = (const float*)d_in[16];
  float* out = (float*)d_out;
  (void)in_sizes; (void)n_in; (void)out_size;

  float *ph, *px, *pg1, *pm, *plog, *pwoP, *pWc, *ppart;
  cudaGetSymbolAddress((void**)&ph,    g_h);
  cudaGetSymbolAddress((void**)&px,    g_x);
  cudaGetSymbolAddress((void**)&pg1,   g_g1);
  cudaGetSymbolAddress((void**)&pm,    g_m);
  cudaGetSymbolAddress((void**)&plog,  g_logits);
  cudaGetSymbolAddress((void**)&pwoP,  g_woP);
  cudaGetSymbolAddress((void**)&pWc,   g_Wc);
  cudaGetSymbolAddress((void**)&ppart, g_part);

  unsigned key0[CC], key1[CC];
  for (int i = 0; i < CC; i++) threefry2x32(0u, 1234u, 0u, (unsigned)i, &key0[i], &key1[i]);

  copy_kernel<<<(BB*HH + 255)/256, 256>>>(backbone, ph, BB*HH);
  wop_kernel<<<(LL*DKV*HH + 255)/256, 256>>>(w_o, pwoP);
  // precompute Wc[l] = wv[l] @ woP[l]
  for (int l = 0; l < LL; l++) {
    sgemm4<0><<<dim3(HH/128, HH/128, 1), 256>>>(
        w_v + (size_t)l*HH*DKV, pwoP + (size_t)l*DKV*HH, pWc + (size_t)l*HH*HH,
        HH, HH, DKV);
  }

  const int MN_H  = BB*HH;   // 262144
  const int MN_I  = BB*II;   // 1048576
  const int MN_V  = BB*VV;   // 262912

  for (int i = 0; i < CC; i++) {
    for (int l = 0; l < LL; l++) {
      rms_kernel<<<BB, 256>>>(ph, w_in + (size_t)l*HH, px);
      // attention collapsed: h += x @ Wc[l]   (split-K 16 -> 256 CTAs)
      sgemm4<0><<<dim3(HH/128, BB/128, 16), 256>>>(px, pWc + (size_t)l*HH*HH, ppart, BB, HH, HH);
      reduce_kernel<<<(MN_H/4 + 255)/256, 256>>>(ppart, ph, ph, nullptr, 16, MN_H/4);
      rms_kernel<<<BB, 256>>>(ph, w_post + (size_t)l*HH, px);
      // gate (split-K 4 -> 256 CTAs)
      sgemm4<0><<<dim3(II/128, BB/128, 4), 256>>>(px, w_g + (size_t)l*HH*II, ppart, BB, II, HH);
      reduce_kernel<<<(MN_I/4 + 255)/256, 256>>>(ppart, pg1, nullptr, nullptr, 4, MN_I/4);
      // up (split-K 4) then swiglu fused in reduce
      sgemm4<0><<<dim3(II/128, BB/128, 4), 256>>>(px, w_u + (size_t)l*HH*II, ppart, BB, II, HH);
      reduce_kernel<<<(MN_I/4 + 255)/256, 256>>>(ppart, pm, nullptr, pg1, 4, MN_I/4);
      // down (split-K 16) + residual
      sgemm4<0><<<dim3(HH/128, BB/128, 16), 256>>>(pm, w_d + (size_t)l*II*HH, ppart, BB, HH, II);
      reduce_kernel<<<(MN_H/4 + 255)/256, 256>>>(ppart, ph, ph, nullptr, 16, MN_H/4);
    }
    rms_kernel<<<BB, 256>>>(ph, fnorm, px);
    // lm head: B stored [V,H] (BT=1), split-K 16 -> 288 CTAs
    sgemm4<1><<<dim3((VV + 127)/128, BB/128, 16), 256>>>(px, lmh + (size_t)i*VV*HH, ppart, BB, VV, HH);
    reduce_kernel<<<(MN_V/4 + 255)/256, 256>>>(ppart, plog, nullptr, nullptr, 16, MN_V/4);
    int do_embed = (i < CC - 1) ? 1 : 0;
    const float* etab = embed + (size_t)(do_embed ? (i + 1) : 0)*VV*HH;
    sample_kernel<<<BB, 256>>>(plog, hist, gsp, i, key0[i], key1[i], out, etab, ph, do_embed);
  }
}

// round 8
// speedup vs baseline: 4.2895x; 2.4189x over previous
#include <cuda_runtime.h>
#include <cuda_fp16.h>
#include <cstdint>

#define BB 256
#define HH 1024
#define LL 4
#define DKV 512
#define II 4096
#define VV 1027
#define CC 16
#define REPW 50
#define INF_F __int_as_float(0x7f800000)

// ---------------- scratch (device globals; no allocation) ----------------
__device__ float g_h[BB*HH];
__device__ float g_g1[BB*II];
__device__ float g_logits[BB*VV];
__device__ float g_woP[LL*DKV*HH];
__device__ float g_part[2105344];            // split-K partials
__device__ __half g_x2[2*BB*HH];
__device__ __half g_v2[2*BB*DKV];
__device__ __half g_m2[2*BB*II];
__device__ __half g_wv2[(size_t)2*LL*DKV*HH];  // [2][L][N=512][K=1024]
__device__ __half g_wo2[(size_t)2*LL*HH*DKV];  // [2][L][N=1024][K=512]
__device__ __half g_wg2[(size_t)2*LL*II*HH];   // [2][L][N=4096][K=1024]
__device__ __half g_wu2[(size_t)2*LL*II*HH];
__device__ __half g_wd2[(size_t)2*LL*HH*II];   // [2][L][N=1024][K=4096]
__device__ __half g_lm2[(size_t)2*CC*VV*HH];   // [2][C][N=1027][K=1024]

// ---------------- threefry2x32 (JAX exact) ----------------
#define TF_ROUND(x0,x1,r) { x0 += x1; x1 = (x1<<(r))|(x1>>(32-(r))); x1 ^= x0; }
__host__ __device__ __forceinline__ void threefry2x32(unsigned k0, unsigned k1,
                                                      unsigned c0, unsigned c1,
                                                      unsigned* o0, unsigned* o1) {
  unsigned ks2 = k0 ^ k1 ^ 0x1BD11BDAu;
  unsigned x0 = c0 + k0, x1 = c1 + k1;
  TF_ROUND(x0,x1,13) TF_ROUND(x0,x1,15) TF_ROUND(x0,x1,26) TF_ROUND(x0,x1,6)
  x0 += k1;  x1 += ks2 + 1u;
  TF_ROUND(x0,x1,17) TF_ROUND(x0,x1,29) TF_ROUND(x0,x1,16) TF_ROUND(x0,x1,24)
  x0 += ks2; x1 += k0 + 2u;
  TF_ROUND(x0,x1,13) TF_ROUND(x0,x1,15) TF_ROUND(x0,x1,26) TF_ROUND(x0,x1,6)
  x0 += k0;  x1 += k1 + 3u;
  TF_ROUND(x0,x1,17) TF_ROUND(x0,x1,29) TF_ROUND(x0,x1,16) TF_ROUND(x0,x1,24)
  x0 += k1;  x1 += ks2 + 4u;
  TF_ROUND(x0,x1,13) TF_ROUND(x0,x1,15) TF_ROUND(x0,x1,26) TF_ROUND(x0,x1,6)
  x0 += ks2; x1 += k0 + 5u;
  *o0 = x0; *o1 = x1;
}

// ---------------- small kernels ----------------
__global__ void copy_kernel(const float* __restrict__ in, float* __restrict__ out, int n) {
  int i = blockIdx.x*blockDim.x + threadIdx.x;
  if (i < n) out[i] = in[i];
}

__global__ void wop_kernel(const float* __restrict__ wo, float* __restrict__ out) {
  int idx = blockIdx.x*blockDim.x + threadIdx.x;
  if (idx >= LL*DKV*HH) return;
  int l = idx >> 19;
  int rem = idx & 524287;
  int s = rem >> 10, n = rem & 1023;
  int hv = s >> 6, d = s & 63;
  const float* w = wo + ((size_t)l << 20);
  out[idx] = w[((hv*2)*64 + d)*1024 + n] + w[((hv*2+1)*64 + d)*1024 + n];
}

__device__ __forceinline__ void split2(float x, __half& h0, __half& h1) {
  h0 = __float2half_rn(x);
  h1 = __float2half_rn(x - __half2float(h0));
}

// transpose-split: W fp32 [K][N] (layer z) -> O fp16 2 planes of [N][K]
__global__ void tsplit_kernel(const float* __restrict__ W, __half* __restrict__ O,
                              int K, int N, size_t wLS, size_t oLS, size_t plane) {
  __shared__ float tile[32][33];
  const float* Wz = W + (size_t)blockIdx.z * wLS;
  __half* Oz = O + (size_t)blockIdx.z * oLS;
  int kb = blockIdx.y*32, nb = blockIdx.x*32;
  int tx = threadIdx.x, ty = threadIdx.y;
  for (int i = ty; i < 32; i += 8)
    tile[i][tx] = Wz[(size_t)(kb+i)*N + nb + tx];
  __syncthreads();
  for (int i = ty; i < 32; i += 8) {
    __half h0, h1; split2(tile[tx][i], h0, h1);
    size_t o = (size_t)(nb + i)*K + kb + tx;
    Oz[o] = h0; Oz[plane + o] = h1;
  }
}

// plain split (already [N][K])
__global__ void split_kernel(const float* __restrict__ in, __half* __restrict__ O,
                             size_t n, size_t plane) {
  size_t i = (size_t)blockIdx.x*blockDim.x + threadIdx.x;
  if (i >= n) return;
  __half h0, h1; split2(in[i], h0, h1);
  O[i] = h0; O[plane + i] = h1;
}

__global__ void rms2_kernel(const float* __restrict__ in, const float* __restrict__ w,
                            __half* __restrict__ O, size_t plane) {
  int b = blockIdx.x, t = threadIdx.x;
  const float* row = in + (size_t)b*HH;
  __shared__ float red[256];
  float s = 0.f;
  #pragma unroll
  for (int j = t; j < HH; j += 256) { float v = row[j]; s += v*v; }
  red[t] = s; __syncthreads();
  for (int st = 128; st > 0; st >>= 1) { if (t < st) red[t] += red[t+st]; __syncthreads(); }
  float r = 1.0f / sqrtf(red[0]*(1.0f/HH) + 1e-6f);
  for (int j = t; j < HH; j += 256) {
    float y = row[j]*r*w[j];
    __half h0, h1; split2(y, h0, h1);
    size_t o = (size_t)b*HH + j;
    O[o] = h0; O[plane + o] = h1;
  }
}

// split-K reduce: + optional residual, optional swiglu(aux), fp32 out and/or fp16x2 out
__global__ void reduce_kernel(const float* __restrict__ P, float* __restrict__ outF,
                              const float* __restrict__ resid, const float* __restrict__ aux,
                              __half* __restrict__ outS, size_t plane,
                              int S, int MN4) {
  int i = blockIdx.x*blockDim.x + threadIdx.x;
  if (i >= MN4) return;
  const float4* P4 = (const float4*)P;
  float4 s = P4[i];
  for (int t = 1; t < S; t++) {
    float4 p = P4[(size_t)t*MN4 + i];
    s.x += p.x; s.y += p.y; s.z += p.z; s.w += p.w;
  }
  if (resid) {
    float4 r = ((const float4*)resid)[i];
    s.x += r.x; s.y += r.y; s.z += r.z; s.w += r.w;
  }
  if (aux) {
    float4 g = ((const float4*)aux)[i];
    float sx = __fdiv_rn(1.f, __fadd_rn(1.f, expf(-g.x)));
    float sy = __fdiv_rn(1.f, __fadd_rn(1.f, expf(-g.y)));
    float sz = __fdiv_rn(1.f, __fadd_rn(1.f, expf(-g.z)));
    float sw = __fdiv_rn(1.f, __fadd_rn(1.f, expf(-g.w)));
    s.x = g.x*sx*s.x; s.y = g.y*sy*s.y; s.z = g.z*sz*s.z; s.w = g.w*sw*s.w;
  }
  if (outF) ((float4*)outF)[i] = s;
  if (outS) {
    float v[4] = {s.x, s.y, s.z, s.w};
    #pragma unroll
    for (int c = 0; c < 4; c++) {
      __half h0, h1; split2(v[c], h0, h1);
      size_t o = (size_t)i*4 + c;
      outS[o] = h0; outS[plane + o] = h1;
    }
  }
}

// ---------------- HMMA fp16x2-split GEMM (LDG->reg->STS double buffer) ----------------
// P[z][256][N] = A @ B^T; A2: 2 fp16 planes [M][K]; B2: 2 fp16 planes [N][K].
// 3 products: (a0,b0), (a0,b1), (a1,b0). CTA 128x128, k-chunk 32.
#define ROWB2 80          // 32 halves (64B) + 16B pad
#define PT    10240       // plane tile bytes: 128*80
#define HG_SMEM 81920     // A: 4*PT, B: 4*PT

__global__ void __launch_bounds__(256, 1)
hgemm_kernel(const __half* __restrict__ A2, const size_t aplane,
             const __half* __restrict__ B2, const size_t bplane,
             float* __restrict__ P, const int N, const int K) {
  extern __shared__ char smem[];
  uint32_t smbase;
  asm("{ .reg .u64 t; cvta.to.shared.u64 t, %1; cvt.u32.u64 %0, t; }"
      : "=r"(smbase) : "l"(smem));

  const int tid = threadIdx.x, wid = tid >> 5, lid = tid & 31;
  const int wm = wid & 1, wn = wid >> 1;          // warp tile: 64m x 32n
  const int m0 = blockIdx.y * 128, n0 = blockIdx.x * 128;
  const int Kc = K / gridDim.z, ks = blockIdx.z * Kc;
  const int NCH = Kc >> 5;
  P += (size_t)blockIdx.z * 256 * N;

  float acc[4][4][4];
  #pragma unroll
  for (int i = 0; i < 4; i++)
    #pragma unroll
    for (int j = 0; j < 4; j++)
      #pragma unroll
      for (int c = 0; c < 4; c++) acc[i][j][c] = 0.f;

  // per-thread load mapping (j in 0..3): idx = tid + 256*j
  //   s = plane (idx>>9), m = row (idx>>2)&127, q = quad (idx&3); quad = 8 halves
  uint4 ra[4], rb[4];
  const __half* aPtr[4];
  const __half* bPtr[4];
  uint32_t stA[4], stB[4];
  #pragma unroll
  for (int j = 0; j < 4; j++) {
    int idx = tid + 256*j;
    int s = idx >> 9, m = (idx >> 2) & 127, q = idx & 3;
    aPtr[j] = A2 + s*aplane + (size_t)(m0 + m)*K + ks + q*8;
    int n = n0 + m; if (n >= N) n = N - 1;     // clamp (cols >= N never stored)
    bPtr[j] = B2 + s*bplane + (size_t)n*K + ks + q*8;
    stA[j] = smbase + s*PT + m*ROWB2 + q*16;
    stB[j] = smbase + 4*PT + s*PT + m*ROWB2 + q*16;
  }

  // lane-constant ldmatrix offsets
  const uint32_t aOff = (uint32_t)((wm*64 + (lid & 15))*ROWB2 + (lid >> 4)*16);
  const uint32_t bOff = (uint32_t)((wn*32 + (lid & 7) + ((lid >> 4) << 3))*ROWB2
                                   + ((lid >> 3) & 1)*16);
  const int pa[3] = {0, 0, 1};
  const int pb[3] = {0, 1, 0};

  // prolog: chunk 0 -> stage 0
  #pragma unroll
  for (int j = 0; j < 4; j++) { ra[j] = *(const uint4*)aPtr[j]; rb[j] = *(const uint4*)bPtr[j]; }
  #pragma unroll
  for (int j = 0; j < 4; j++) {
    *(uint4*)(smem + (stA[j] - smbase)) = ra[j];
    *(uint4*)(smem + (stB[j] - smbase)) = rb[j];
  }
  __syncthreads();

  for (int ch = 0; ch < NCH; ch++) {
    const int cur = ch & 1;
    const bool hasNext = (ch + 1 < NCH);
    if (hasNext) {
      #pragma unroll
      for (int j = 0; j < 4; j++) {
        ra[j] = *(const uint4*)(aPtr[j] + (ch + 1)*32);
        rb[j] = *(const uint4*)(bPtr[j] + (ch + 1)*32);
      }
    }
    // compute current stage
    const uint32_t smA = smbase + cur*2*PT;
    const uint32_t smB = smbase + 4*PT + cur*2*PT;
    #pragma unroll
    for (int p = 0; p < 3; p++) {
      const uint32_t aPl = smA + pa[p]*PT + aOff;
      const uint32_t bPl = smB + pb[p]*PT + bOff;
      #pragma unroll
      for (int kk = 0; kk < 2; kk++) {
        uint32_t a[4][4], b[2][4];
        #pragma unroll
        for (int mf = 0; mf < 4; mf++) {
          asm volatile("ldmatrix.sync.aligned.m8n8.x4.shared.b16 {%0,%1,%2,%3}, [%4];"
            : "=r"(a[mf][0]), "=r"(a[mf][1]), "=r"(a[mf][2]), "=r"(a[mf][3])
            : "r"(aPl + mf*(16*ROWB2) + kk*32));
        }
        #pragma unroll
        for (int g = 0; g < 2; g++) {
          asm volatile("ldmatrix.sync.aligned.m8n8.x4.shared.b16 {%0,%1,%2,%3}, [%4];"
            : "=r"(b[g][0]), "=r"(b[g][1]), "=r"(b[g][2]), "=r"(b[g][3])
            : "r"(bPl + g*(16*ROWB2) + kk*32));
        }
        #pragma unroll
        for (int mf = 0; mf < 4; mf++)
          #pragma unroll
          for (int nf = 0; nf < 4; nf++) {
            uint32_t b0 = b[nf >> 1][2*(nf & 1)];
            uint32_t b1 = b[nf >> 1][2*(nf & 1) + 1];
            asm volatile(
              "mma.sync.aligned.m16n8k16.row.col.f32.f16.f16.f32 "
              "{%0,%1,%2,%3}, {%4,%5,%6,%7}, {%8,%9}, {%0,%1,%2,%3};"
              : "+f"(acc[mf][nf][0]), "+f"(acc[mf][nf][1]),
                "+f"(acc[mf][nf][2]), "+f"(acc[mf][nf][3])
              : "r"(a[mf][0]), "r"(a[mf][1]), "r"(a[mf][2]), "r"(a[mf][3]),
                "r"(b0), "r"(b1));
          }
      }
    }
    // store next chunk into the other stage (readers of that stage finished
    // before the trailing __syncthreads of the previous iteration)
    if (hasNext) {
      const int nxt = cur ^ 1;
      #pragma unroll
      for (int j = 0; j < 4; j++) {
        *(uint4*)(smem + (stA[j] - smbase) + nxt*2*PT) = ra[j];
        *(uint4*)(smem + (stB[j] - smbase) + nxt*2*PT) = rb[j];
      }
    }
    __syncthreads();
  }

  // epilogue: write fp32 partials
  const int mr = lid >> 2, nc2 = 2*(lid & 3);
  #pragma unroll
  for (int mf = 0; mf < 4; mf++) {
    int gm = m0 + wm*64 + mf*16 + mr;
    float* r0 = P + (size_t)gm * N;
    float* r1 = P + (size_t)(gm + 8) * N;
    #pragma unroll
    for (int nf = 0; nf < 4; nf++) {
      int gn = n0 + wn*32 + nf*8 + nc2;
      if (gn < N)     { r0[gn]   = acc[mf][nf][0]; r1[gn]   = acc[mf][nf][2]; }
      if (gn + 1 < N) { r0[gn+1] = acc[mf][nf][1]; r1[gn+1] = acc[mf][nf][3]; }
    }
  }
}

// ---------------- rep penalty + top-k + top-p + gumbel sample + embed gather ----------
__global__ void sample_kernel(const float* __restrict__ logits, const int* __restrict__ hist,
                              const int* __restrict__ gsp, int step,
                              unsigned k0, unsigned k1,
                              float* __restrict__ out,
                              const float* __restrict__ embed, float* __restrict__ hnext,
                              int do_embed) {
  int b = blockIdx.x, t = threadIdx.x;
  __shared__ float sl[VV];
  __shared__ float wk[VV];
  __shared__ float cv[VV];
  __shared__ int   ci[VV];
  __shared__ float rv[256];
  __shared__ int   ri[256];
  __shared__ int   cnt;
  __shared__ float thrS;

  for (int v = t; v < VV; v += 256) sl[v] = logits[(size_t)b*VV + v];
  if (t == 0) cnt = 0;
  __syncthreads();

  int gs = *gsp;
  int w0 = gs - REPW; if (w0 < 0) w0 = 0;
  int wn = gs - w0;
  float cur = 0.f; int tk = -1;
  if (t < wn) { tk = hist[((size_t)b*200 + w0 + t)*CC + step]; cur = sl[tk]; }
  __syncthreads();
  if (t < wn) {
    float nw = (cur < 0.f) ? __fmul_rn(cur, 1.1f) : __fdiv_rn(cur, 1.1f);
    sl[tk] = nw;
  }
  __syncthreads();

  for (int v = t; v < VV; v += 256) { float x = __fdiv_rn(sl[v], 0.8f); sl[v] = x; wk[v] = x; }
  __syncthreads();

  for (int it = 0; it < 30; it++) {
    float bv = -INF_F; int bi = 0;
    for (int v = t; v < VV; v += 256) { float x = wk[v]; if (x > bv) { bv = x; bi = v; } }
    rv[t] = bv; ri[t] = bi; __syncthreads();
    for (int st = 128; st > 0; st >>= 1) {
      if (t < st) { if (rv[t+st] > rv[t]) { rv[t] = rv[t+st]; ri[t] = ri[t+st]; } }
      __syncthreads();
    }
    if (t == 0) { wk[ri[0]] = -INF_F; if (it == 29) thrS = rv[0]; }
    __syncthreads();
  }
  float thr = thrS;

  for (int v = t; v < VV; v += 256) {
    float x = sl[v];
    if (x >= thr) { int p = atomicAdd(&cnt, 1); cv[p] = x; ci[p] = v; }
  }
  __syncthreads();
  int n = cnt;

  if (t == 0) {
    for (int i = 1; i < n; i++) {
      float kv = cv[i]; int ki = ci[i]; int j = i - 1;
      while (j >= 0 && (cv[j] > kv || (cv[j] == kv && ci[j] > ki))) {
        cv[j+1] = cv[j]; ci[j+1] = ci[j]; j--;
      }
      cv[j+1] = kv; ci[j+1] = ki;
    }
    float mx = cv[n-1];
    float total = 0.f;
    for (int j = 0; j < n; j++) { wk[j] = expf(cv[j] - mx); total += wk[j]; }
    float run = 0.f;
    for (int j = 0; j < n; j++) {
      run = __fadd_rn(run, __fdiv_rn(wk[j], total));
      if (run <= 0.4f) cv[j] = -INF_F;
    }
  }
  __syncthreads();

  float bs = -INF_F; int bidx = 0x7fffffff;
  for (int j = t; j < n; j += 256) {
    float x = cv[j];
    if (x > -INF_F) {
      unsigned m = (unsigned)(b*VV + ci[j]);
      unsigned o0, o1;
      threefry2x32(k0, k1, 0u, m, &o0, &o1);
      unsigned bits = o0 ^ o1;
      float u = __uint_as_float((bits >> 9) | 0x3f800000u) - 1.0f;
      u = __fadd_rn(__fmul_rn(u, 1.0f), 1.17549435e-38f);
      u = fmaxf(1.17549435e-38f, u);
      float g = -logf(-logf(u));
      float sc = __fadd_rn(x, g);
      if (sc > bs || (sc == bs && ci[j] < bidx)) { bs = sc; bidx = ci[j]; }
    }
  }
  rv[t] = bs; ri[t] = bidx; __syncthreads();
  for (int st = 128; st > 0; st >>= 1) {
    if (t < st) {
      if (rv[t+st] > rv[t] || (rv[t+st] == rv[t] && ri[t+st] < ri[t])) {
        rv[t] = rv[t+st]; ri[t] = ri[t+st];
      }
    }
    __syncthreads();
  }
  int best = ri[0];
  if (t == 0) out[b*CC + step] = (float)best;
  if (do_embed) {
    const float* e = embed + (size_t)best*HH;
    for (int j = t; j < HH; j += 256) hnext[(size_t)b*HH + j] = e[j];
  }
}

// ---------------- driver ----------------
extern "C" void kernel_launch(void* const* d_in, const int* in_sizes, int n_in,
                              void* d_out, int out_size) {
  const float* backbone = (const float*)d_in[0];
  const int*   hist     = (const int*)d_in[1];
  const int*   gsp      = (const int*)d_in[2];
  const float* embed    = (const float*)d_in[3];
  const float* lmh      = (const float*)d_in[4];
  const float* w_in     = (const float*)d_in[5];
  const float* w_v      = (const float*)d_in[8];
  const float* w_o      = (const float*)d_in[11];
  const float* w_post   = (const float*)d_in[12];
  const float* w_g      = (const float*)d_in[13];
  const float* w_u      = (const float*)d_in[14];
  const float* w_d      = (const float*)d_in[15];
  const float* fnorm    = (const float*)d_in[16];
  float* out = (float*)d_out;
  (void)in_sizes; (void)n_in; (void)out_size;

  float *ph, *pg1, *plog, *pwoP, *ppart;
  __half *px2, *pv2, *pm2, *pwv2, *pwo2, *pwg2, *pwu2, *pwd2, *plm2;
  cudaGetSymbolAddress((void**)&ph,    g_h);
  cudaGetSymbolAddress((void**)&pg1,   g_g1);
  cudaGetSymbolAddress((void**)&plog,  g_logits);
  cudaGetSymbolAddress((void**)&pwoP,  g_woP);
  cudaGetSymbolAddress((void**)&ppart, g_part);
  cudaGetSymbolAddress((void**)&px2,   g_x2);
  cudaGetSymbolAddress((void**)&pv2,   g_v2);
  cudaGetSymbolAddress((void**)&pm2,   g_m2);
  cudaGetSymbolAddress((void**)&pwv2,  g_wv2);
  cudaGetSymbolAddress((void**)&pwo2,  g_wo2);
  cudaGetSymbolAddress((void**)&pwg2,  g_wg2);
  cudaGetSymbolAddress((void**)&pwu2,  g_wu2);
  cudaGetSymbolAddress((void**)&pwd2,  g_wd2);
  cudaGetSymbolAddress((void**)&plm2,  g_lm2);

  cudaFuncSetAttribute(hgemm_kernel, cudaFuncAttributeMaxDynamicSharedMemorySize, HG_SMEM);

  unsigned key0[CC], key1[CC];
  for (int i = 0; i < CC; i++) threefry2x32(0u, 1234u, 0u, (unsigned)i, &key0[i], &key1[i]);

  const size_t PL_X = (size_t)BB*HH, PL_V = (size_t)BB*DKV, PL_M = (size_t)BB*II;
  const size_t PLW_V = (size_t)LL*DKV*HH, PLW_O = (size_t)LL*HH*DKV;
  const size_t PLW_G = (size_t)LL*II*HH,  PLW_D = (size_t)LL*HH*II;
  const size_t PLW_L = (size_t)CC*VV*HH;

  // ---- precompute: fold wo, transpose-split all weights into fp16x2 planes ----
  copy_kernel<<<(BB*HH + 255)/256, 256>>>(backbone, ph, BB*HH);
  wop_kernel<<<(LL*DKV*HH + 255)/256, 256>>>(w_o, pwoP);
  dim3 tb(32, 8);
  tsplit_kernel<<<dim3(DKV/32, HH/32, LL), tb>>>(w_v, pwv2, HH, DKV,
      (size_t)HH*DKV, (size_t)DKV*HH, PLW_V);
  tsplit_kernel<<<dim3(HH/32, DKV/32, LL), tb>>>(pwoP, pwo2, DKV, HH,
      (size_t)DKV*HH, (size_t)HH*DKV, PLW_O);
  tsplit_kernel<<<dim3(II/32, HH/32, LL), tb>>>(w_g, pwg2, HH, II,
      (size_t)HH*II, (size_t)II*HH, PLW_G);
  tsplit_kernel<<<dim3(II/32, HH/32, LL), tb>>>(w_u, pwu2, HH, II,
      (size_t)HH*II, (size_t)II*HH, PLW_G);
  tsplit_kernel<<<dim3(HH/32, II/32, LL), tb>>>(w_d, pwd2, II, HH,
      (size_t)II*HH, (size_t)HH*II, PLW_D);
  split_kernel<<<(unsigned)((PLW_L + 255)/256), 256>>>(lmh, plm2, PLW_L, PLW_L);

  const int MN_H = BB*HH, MN_V = BB*DKV, MN_I = BB*II, MN_L = BB*VV;

  for (int i = 0; i < CC; i++) {
    for (int l = 0; l < LL; l++) {
      rms2_kernel<<<BB, 256>>>(ph, w_in + (size_t)l*HH, px2, PL_X);
      // v = x @ wv   (N=512, K=1024, S=16 -> 128 CTAs)
      hgemm_kernel<<<dim3(4, 2, 16), 256, HG_SMEM>>>(px2, PL_X,
          pwv2 + (size_t)l*DKV*HH, PLW_V, ppart, DKV, HH);
      reduce_kernel<<<(MN_V/4 + 255)/256, 256>>>(ppart, nullptr, nullptr, nullptr,
          pv2, PL_V, 16, MN_V/4);
      // h += v @ woP (N=1024, K=512, S=8 -> 128 CTAs)
      hgemm_kernel<<<dim3(8, 2, 8), 256, HG_SMEM>>>(pv2, PL_V,
          pwo2 + (size_t)l*HH*DKV, PLW_O, ppart, HH, DKV);
      reduce_kernel<<<(MN_H/4 + 255)/256, 256>>>(ppart, ph, ph, nullptr,
          nullptr, 0, 8, MN_H/4);
      rms2_kernel<<<BB, 256>>>(ph, w_post + (size_t)l*HH, px2, PL_X);
      // gate (N=4096, K=1024, S=2 -> 128 CTAs)
      hgemm_kernel<<<dim3(32, 2, 2), 256, HG_SMEM>>>(px2, PL_X,
          pwg2 + (size_t)l*II*HH, PLW_G, ppart, II, HH);
      reduce_kernel<<<(MN_I/4 + 255)/256, 256>>>(ppart, pg1, nullptr, nullptr,
          nullptr, 0, 2, MN_I/4);
      // up (S=2) + swiglu -> m fp16 planes
      hgemm_kernel<<<dim3(32, 2, 2), 256, HG_SMEM>>>(px2, PL_X,
          pwu2 + (size_t)l*II*HH, PLW_G, ppart, II, HH);
      reduce_kernel<<<(MN_I/4 + 255)/256, 256>>>(ppart, nullptr, nullptr, pg1,
          pm2, PL_M, 2, MN_I/4);
      // down (N=1024, K=4096, S=8 -> 128 CTAs) + residual
      hgemm_kernel<<<dim3(8, 2, 8), 256, HG_SMEM>>>(pm2, PL_M,
          pwd2 + (size_t)l*HH*II, PLW_D, ppart, HH, II);
      reduce_kernel<<<(MN_H/4 + 255)/256, 256>>>(ppart, ph, ph, nullptr,
          nullptr, 0, 8, MN_H/4);
    }
    rms2_kernel<<<BB, 256>>>(ph, fnorm, px2, PL_X);
    // lm head (N=1027, K=1024, S=8 -> 144 CTAs)
    hgemm_kernel<<<dim3(9, 2, 8), 256, HG_SMEM>>>(px2, PL_X,
        plm2 + (size_t)i*VV*HH, PLW_L, ppart, VV, HH);
    reduce_kernel<<<(MN_L/4 + 255)/256, 256>>>(ppart, plog, nullptr, nullptr,
        nullptr, 0, 8, MN_L/4);
    int do_embed = (i < CC - 1) ? 1 : 0;
    const float* etab = embed + (size_t)(do_embed ? (i + 1) : 0)*VV*HH;
    sample_kernel<<<BB, 256>>>(plog, hist, gsp, i, key0[i], key1[i], out, etab, ph, do_embed);
  }
}